// round 1
// baseline (speedup 1.0000x reference)
#include <cuda_runtime.h>
#include <cuda_bf16.h>

// Elementwise: y = (x + 1) * 2 / 3; if (y > 0) y -= 5;
// 8192*8192 fp32 = 67,108,864 elements. Pure HBM-streaming kernel.
// Vectorized float4 grid-stride loop.

__global__ __launch_bounds__(256) void ew_kernel(const float4* __restrict__ x,
                                                 float4* __restrict__ out,
                                                 int n4) {
    const float c = 2.0f / 3.0f;  // (x+1)*2/3 == x*(2/3) + (2/3)
    int i = blockIdx.x * blockDim.x + threadIdx.x;
    int stride = gridDim.x * blockDim.x;
    for (; i < n4; i += stride) {
        float4 v = x[i];
        float4 r;
        r.x = fmaf(v.x, c, c);
        r.y = fmaf(v.y, c, c);
        r.z = fmaf(v.z, c, c);
        r.w = fmaf(v.w, c, c);
        if (r.x > 0.0f) r.x -= 5.0f;
        if (r.y > 0.0f) r.y -= 5.0f;
        if (r.z > 0.0f) r.z -= 5.0f;
        if (r.w > 0.0f) r.w -= 5.0f;
        out[i] = r;
    }
}

extern "C" void kernel_launch(void* const* d_in, const int* in_sizes, int n_in,
                              void* d_out, int out_size) {
    const float4* x = (const float4*)d_in[0];
    float4* out = (float4*)d_out;
    int n = in_sizes[0];          // 67,108,864 (divisible by 4)
    int n4 = n >> 2;              // 16,777,216 float4s

    const int threads = 256;
    // ~2 waves of full-chip residency: 148 SMs * 2048 threads / 256 = 1184 blocks/wave.
    // Give each thread a handful of iterations to amortize loop overhead.
    int blocks = (n4 + threads * 8 - 1) / (threads * 8);  // 8 float4 per thread
    if (blocks < 1) blocks = 1;
    ew_kernel<<<blocks, threads>>>(x, out, n4);
}

// round 2
// speedup vs baseline: 1.0012x; 1.0012x over previous
#include <cuda_runtime.h>
#include <cuda_bf16.h>

// Elementwise: y = (x + 1) * 2 / 3; if (y > 0) y -= 5;
// 8192*8192 fp32 = 67,108,864 elements (16,777,216 float4s).
// Pure HBM-streaming. Flat (no-loop) kernel: 4 independent LDG.128 per
// thread for deep MLP, streaming cache hints (evict-first L2).

__device__ __forceinline__ float4 transform4(float4 v) {
    const float c = 2.0f / 3.0f;   // (x+1)*2/3 == fma(x, 2/3, 2/3)
    float4 r;
    r.x = fmaf(v.x, c, c);
    r.y = fmaf(v.y, c, c);
    r.z = fmaf(v.z, c, c);
    r.w = fmaf(v.w, c, c);
    if (r.x > 0.0f) r.x -= 5.0f;
    if (r.y > 0.0f) r.y -= 5.0f;
    if (r.z > 0.0f) r.z -= 5.0f;
    if (r.w > 0.0f) r.w -= 5.0f;
    return r;
}

// Flat kernel: each block handles 256 threads * 4 float4 = 1024 float4s.
// Requires n4 % 1024 == 0 (true here: 16,777,216 / 1024 = 16384 blocks).
__global__ __launch_bounds__(256) void ew_flat(const float4* __restrict__ x,
                                               float4* __restrict__ out) {
    int base = blockIdx.x * (256 * 4) + threadIdx.x;
    // 4 independent streaming loads issued back-to-back (MLP=4)
    float4 v0 = __ldcs(x + base + 0 * 256);
    float4 v1 = __ldcs(x + base + 1 * 256);
    float4 v2 = __ldcs(x + base + 2 * 256);
    float4 v3 = __ldcs(x + base + 3 * 256);
    float4 r0 = transform4(v0);
    float4 r1 = transform4(v1);
    float4 r2 = transform4(v2);
    float4 r3 = transform4(v3);
    __stcs(out + base + 0 * 256, r0);
    __stcs(out + base + 1 * 256, r1);
    __stcs(out + base + 2 * 256, r2);
    __stcs(out + base + 3 * 256, r3);
}

// Fallback grid-stride (correctness for any size)
__global__ __launch_bounds__(256) void ew_gs(const float4* __restrict__ x,
                                             float4* __restrict__ out, int n4) {
    int i = blockIdx.x * blockDim.x + threadIdx.x;
    int stride = gridDim.x * blockDim.x;
    for (; i < n4; i += stride) {
        __stcs(out + i, transform4(__ldcs(x + i)));
    }
}

__global__ void ew_scalar_tail(const float* __restrict__ x,
                               float* __restrict__ out, int start, int n) {
    int i = start + blockIdx.x * blockDim.x + threadIdx.x;
    if (i < n) {
        const float c = 2.0f / 3.0f;
        float r = fmaf(x[i], c, c);
        if (r > 0.0f) r -= 5.0f;
        out[i] = r;
    }
}

extern "C" void kernel_launch(void* const* d_in, const int* in_sizes, int n_in,
                              void* d_out, int out_size) {
    const float* x = (const float*)d_in[0];
    float* out = (float*)d_out;
    int n = in_sizes[0];          // 67,108,864
    int n4 = n >> 2;

    const int per_block = 256 * 4;  // float4s per block
    if ((n % 4) == 0 && (n4 % per_block) == 0) {
        int blocks = n4 / per_block;  // 16384
        ew_flat<<<blocks, 256>>>((const float4*)x, (float4*)out);
    } else {
        int n4f = n >> 2;
        if (n4f > 0) {
            int blocks = (n4f + 256 * 8 - 1) / (256 * 8);
            ew_gs<<<blocks, 256>>>((const float4*)x, (float4*)out, n4f);
        }
        int tail = n - (n4f << 2);
        if (tail > 0) {
            ew_scalar_tail<<<(tail + 255) / 256, 256>>>(x, out, n4f << 2, n);
        }
    }
}